// round 14
// baseline (speedup 1.0000x reference)
#include <cuda_runtime.h>
#include <cstdint>

// SNN: x[B,5] -> L1(32) -> spike(dot>=2) -> L2(32) -> L3(16) -> L4(10) -> spike.
// R8 body (const W1, 1 row/thread, direct __ldg x, zero-fill + rare scatter,
// popc gate: sound bound, rel_err==0 across R3-R13) with:
//  - minpop computed redundantly PER WARP (no barrier, no setup node; W2 scan
//    is L2-hot and overlaps the warp's own FMA block)
//  - mask bits from sign of fl(a-2) (exact; replaces 13-cyc FSETP guards)
//  - float4 LDC.128 weight loads

__constant__ __align__(16) float cW1[160];

// exact layers 2-4 (rare, ~1e-4 of rows); identical to R1-R13 validated code.
__device__ __noinline__ unsigned rare_path(unsigned mask1,
                                           const float* __restrict__ W2,
                                           const float* __restrict__ W3,
                                           const float* __restrict__ W4)
{
    unsigned mask2 = 0;
    #pragma unroll
    for (int jc = 0; jc < 32; jc += 8) {
        float acc[8] = {0, 0, 0, 0, 0, 0, 0, 0};
        unsigned mm = mask1;
        while (mm) {
            int i = __ffs(mm) - 1; mm &= mm - 1;
            #pragma unroll
            for (int j = 0; j < 8; j++) acc[j] += W2[(jc + j) * 32 + i];
        }
        #pragma unroll
        for (int j = 0; j < 8; j++)
            if (acc[j] >= 2.0f) mask2 |= 1u << (jc + j);
    }
    if (!mask2) return 0;

    unsigned mask3 = 0;
    #pragma unroll
    for (int jc = 0; jc < 16; jc += 8) {
        float acc[8] = {0, 0, 0, 0, 0, 0, 0, 0};
        unsigned mm = mask2;
        while (mm) {
            int i = __ffs(mm) - 1; mm &= mm - 1;
            #pragma unroll
            for (int j = 0; j < 8; j++) acc[j] += W3[(jc + j) * 32 + i];
        }
        #pragma unroll
        for (int j = 0; j < 8; j++)
            if (acc[j] >= 2.0f) mask3 |= 1u << (jc + j);
    }
    if (!mask3) return 0;

    float acc4[10];
    #pragma unroll
    for (int j = 0; j < 10; j++) acc4[j] = 0.0f;
    unsigned mm = mask3;
    while (mm) {
        int i = __ffs(mm) - 1; mm &= mm - 1;
        #pragma unroll
        for (int j = 0; j < 10; j++) acc4[j] += W4[j * 16 + i];
    }
    unsigned om = 0;
    #pragma unroll
    for (int j = 0; j < 10; j++)
        if (acc4[j] >= 2.0f) om |= 1u << j;
    return om;
}

#define BT 256

__global__ __launch_bounds__(BT)
void snn_kernel(const float* __restrict__ x,
                const float* __restrict__ W2,
                const float* __restrict__ W3,
                const float* __restrict__ W4,
                float* __restrict__ out)
{
    const int tid  = threadIdx.x;
    const int lane = tid & 31;
    const size_t row = (size_t)blockIdx.x * BT + tid;

    // zero-fill this block's output tile: 640 coalesced STG.128 (validated R8)
    {
        float4* ov = reinterpret_cast<float4*>(out + (size_t)blockIdx.x * (BT * 10));
        const float4 z = make_float4(0.f, 0.f, 0.f, 0.f);
        #pragma unroll
        for (int i = tid; i < BT * 10 / 4; i += BT) ov[i] = z;
    }

    // per-warp W2 colmax scan (coalesced 128B lines, L2-hot; independent of
    // the FMA block below so it overlaps). No barrier anywhere before use.
    float cmx = W2[lane];
    #pragma unroll
    for (int j = 1; j < 32; j++) cmx = fmaxf(cmx, W2[j * 32 + lane]);

    // direct x reads
    const float* xr = x + row * 5;
    const float x0 = __ldg(xr + 0);
    const float x1 = __ldg(xr + 1);
    const float x2 = __ldg(xr + 2);
    const float x3 = __ldg(xr + 3);
    const float x4 = __ldg(xr + 4);

    // Layer 1: dense 32x5, weights via LDC.128. Same mul->fma order as the
    // reference-validated R2/R8/R9 kernels. Spike bit = sign of fl(a-2):
    // exact (monotone rounding; a==2 -> +0 -> non-negative -> spike).
    unsigned mask1 = 0;
    const float4* cw4 = reinterpret_cast<const float4*>(cW1);
    #pragma unroll
    for (int c = 0; c < 8; c++) {
        float w[20];
        #pragma unroll
        for (int q = 0; q < 5; q++) {
            float4 t = cw4[c * 5 + q];
            w[q * 4 + 0] = t.x; w[q * 4 + 1] = t.y;
            w[q * 4 + 2] = t.z; w[q * 4 + 3] = t.w;
        }
        #pragma unroll
        for (int r = 0; r < 4; r++) {
            float a = w[r * 5 + 0] * x0;
            a = fmaf(w[r * 5 + 1], x1, a);
            a = fmaf(w[r * 5 + 2], x2, a);
            a = fmaf(w[r * 5 + 3], x3, a);
            a = fmaf(w[r * 5 + 4], x4, a);
            int d = __float_as_int(a - 2.0f);      // sign bit 0 <=> a >= 2
            mask1 |= ((unsigned)(~d) >> 31) << (4 * c + r);
        }
    }

    // finish minpop per warp (shuffle reduce + tiny scalar loop)
    #pragma unroll
    for (int s = 16; s > 0; s >>= 1)
        cmx = fmaxf(cmx, __shfl_xor_sync(0xffffffffu, cmx, s));
    int mp = 1;  // smallest popc whose bound popc*cmax could round to >= 2
    while (mp < 33 && (float)mp * cmx < 1.99f) mp++;

    // gate (~1e-4 taken); rare path exact. out-zeroing precedes in program
    // order within this thread, so the scatter overwrite is safe.
    if (__popc(mask1) >= mp) {
        unsigned om = rare_path(mask1, W2, W3, W4);
        if (om) {
            float* o = out + row * 10;
            #pragma unroll
            for (int j = 0; j < 10; j++)
                o[j] = ((om >> j) & 1u) ? 1.0f : 0.0f;
        }
    }
}

extern "C" void kernel_launch(void* const* d_in, const int* in_sizes, int n_in,
                              void* d_out, int out_size)
{
    const float* x  = (const float*)d_in[0];
    const float* W1 = (const float*)d_in[1];
    const float* W2 = (const float*)d_in[2];
    const float* W3 = (const float*)d_in[3];
    const float* W4 = (const float*)d_in[4];
    float* out = (float*)d_out;

    const int B = in_sizes[0] / 5;        // 2097152
    const int grid = B / BT;              // 8192

    cudaMemcpyToSymbolAsync(cW1, W1, 160 * sizeof(float), 0,
                            cudaMemcpyDeviceToDevice, 0);
    snn_kernel<<<grid, BT>>>(x, W2, W3, W4, out);
}

// round 15
// speedup vs baseline: 1.0500x; 1.0500x over previous
#include <cuda_runtime.h>
#include <cstdint>

// SNN: x[B,5] -> L1(32) -> spike(dot>=2) -> L2(32) -> L3(16) -> L4(10) -> spike.
// R8 body (const W1, 1 row/thread, zero-fill + rare scatter, popc gate with
// setup-kernel minpop: sound bound, rel_err==0 across R3-R14) + shared-staged
// x (coalesced LDG.128 -> STS.128 -> conflict-free stride-5 LDS.32), replacing
// the stride-5 direct LDGs whose sector replays dominated L1 (~60%).

__constant__ __align__(16) float cW1[160];
__device__ int g_minpop;

__global__ void setup_kernel(const float* __restrict__ W2) {
    int i = threadIdx.x;
    float mx = W2[i];
    #pragma unroll
    for (int j = 1; j < 32; j++) mx = fmaxf(mx, W2[j * 32 + i]);
    #pragma unroll
    for (int s = 16; s > 0; s >>= 1)
        mx = fmaxf(mx, __shfl_xor_sync(0xffffffffu, mx, s));
    if (i == 0) {
        int mp = 1;  // smallest popc whose bound popc*cmax could round to >= 2
        while (mp < 33 && (float)mp * mx < 1.99f) mp++;
        g_minpop = mp;
    }
}

// exact layers 2-4 (rare, ~1e-4 of rows); identical to R1-R14 validated code.
__device__ __noinline__ unsigned rare_path(unsigned mask1,
                                           const float* __restrict__ W2,
                                           const float* __restrict__ W3,
                                           const float* __restrict__ W4)
{
    unsigned mask2 = 0;
    #pragma unroll
    for (int jc = 0; jc < 32; jc += 8) {
        float acc[8] = {0, 0, 0, 0, 0, 0, 0, 0};
        unsigned mm = mask1;
        while (mm) {
            int i = __ffs(mm) - 1; mm &= mm - 1;
            #pragma unroll
            for (int j = 0; j < 8; j++) acc[j] += W2[(jc + j) * 32 + i];
        }
        #pragma unroll
        for (int j = 0; j < 8; j++)
            if (acc[j] >= 2.0f) mask2 |= 1u << (jc + j);
    }
    if (!mask2) return 0;

    unsigned mask3 = 0;
    #pragma unroll
    for (int jc = 0; jc < 16; jc += 8) {
        float acc[8] = {0, 0, 0, 0, 0, 0, 0, 0};
        unsigned mm = mask2;
        while (mm) {
            int i = __ffs(mm) - 1; mm &= mm - 1;
            #pragma unroll
            for (int j = 0; j < 8; j++) acc[j] += W3[(jc + j) * 32 + i];
        }
        #pragma unroll
        for (int j = 0; j < 8; j++)
            if (acc[j] >= 2.0f) mask3 |= 1u << (jc + j);
    }
    if (!mask3) return 0;

    float acc4[10];
    #pragma unroll
    for (int j = 0; j < 10; j++) acc4[j] = 0.0f;
    unsigned mm = mask3;
    while (mm) {
        int i = __ffs(mm) - 1; mm &= mm - 1;
        #pragma unroll
        for (int j = 0; j < 10; j++) acc4[j] += W4[j * 16 + i];
    }
    unsigned om = 0;
    #pragma unroll
    for (int j = 0; j < 10; j++)
        if (acc4[j] >= 2.0f) om |= 1u << j;
    return om;
}

#define BT 256

__global__ __launch_bounds__(BT)
void snn_kernel(const float* __restrict__ x,
                const float* __restrict__ W2,
                const float* __restrict__ W3,
                const float* __restrict__ W4,
                float* __restrict__ out)
{
    __shared__ float sX[BT * 5];   // 1280 floats = 320 float4

    const int tid = threadIdx.x;
    const size_t row = (size_t)blockIdx.x * BT + tid;
    const int mp = g_minpop;

    // issue the coalesced x-tile loads FIRST (latency hides under zero-fill)
    const float4* xv = reinterpret_cast<const float4*>(x) +
                       (size_t)blockIdx.x * (BT * 5 / 4);
    float4 v0 = xv[tid];
    float4 v1;
    if (tid < 64) v1 = xv[tid + 256];

    // zero-fill this block's output tile: 640 coalesced STG.128 (independent
    // of the loads above; fire-and-forget). Rare scatter after the barrier
    // overwrites the handful of nonzero rows (pattern validated R3-R14).
    {
        float4* ov = reinterpret_cast<float4*>(out + (size_t)blockIdx.x * (BT * 10));
        const float4 z = make_float4(0.f, 0.f, 0.f, 0.f);
        ov[tid] = z;
        ov[tid + 256] = z;
        if (tid < 128) ov[tid + 512] = z;
    }

    // stage x into shared
    {
        float4* sx4 = reinterpret_cast<float4*>(sX);
        sx4[tid] = v0;
        if (tid < 64) sx4[tid + 256] = v1;
    }
    __syncthreads();

    // conflict-free LDS.32 (stride 5, coprime with 32 banks)
    const float x0 = sX[tid * 5 + 0];
    const float x1 = sX[tid * 5 + 1];
    const float x2 = sX[tid * 5 + 2];
    const float x3 = sX[tid * 5 + 3];
    const float x4 = sX[tid * 5 + 4];

    // Layer 1: dense 32x5, weights from __constant__ (R8-validated form/order)
    unsigned mask1 = 0;
    #pragma unroll
    for (int o = 0; o < 32; o++) {
        float a = cW1[o * 5 + 0] * x0;
        a = fmaf(cW1[o * 5 + 1], x1, a);
        a = fmaf(cW1[o * 5 + 2], x2, a);
        a = fmaf(cW1[o * 5 + 3], x3, a);
        a = fmaf(cW1[o * 5 + 4], x4, a);
        if (a >= 2.0f) mask1 |= 1u << o;
    }

    // gate (~1e-4 taken); rare path exact. Zero-fill STGs precede the
    // barrier, so the scatter overwrite is ordered.
    if (__popc(mask1) >= mp) {
        unsigned om = rare_path(mask1, W2, W3, W4);
        if (om) {
            float* o = out + row * 10;
            #pragma unroll
            for (int j = 0; j < 10; j++)
                o[j] = ((om >> j) & 1u) ? 1.0f : 0.0f;
        }
    }
}

extern "C" void kernel_launch(void* const* d_in, const int* in_sizes, int n_in,
                              void* d_out, int out_size)
{
    const float* x  = (const float*)d_in[0];
    const float* W1 = (const float*)d_in[1];
    const float* W2 = (const float*)d_in[2];
    const float* W3 = (const float*)d_in[3];
    const float* W4 = (const float*)d_in[4];
    float* out = (float*)d_out;

    const int B = in_sizes[0] / 5;        // 2097152
    const int grid = B / BT;              // 8192

    cudaMemcpyToSymbolAsync(cW1, W1, 160 * sizeof(float), 0,
                            cudaMemcpyDeviceToDevice, 0);
    setup_kernel<<<1, 32>>>(W2);
    snn_kernel<<<grid, BT>>>(x, W2, W3, W4, out);
}

// round 16
// speedup vs baseline: 1.0798x; 1.0284x over previous
#include <cuda_runtime.h>
#include <cstdint>

// SNN: x[B,5] -> L1(32) -> spike(dot>=2) -> L2(32) -> L3(16) -> L4(10) -> spike.
// Layer 1 in f32x2: two ADJACENT output neurons per packed register pair.
// Weights pre-paired in setup kernel (no per-use packing), x packed once.
// Per-lane arithmetic order identical to the R2/R8-validated scalar kernel.
// Layers 2-4 gated by popc >= g_minpop (sound bound, rel_err==0 R3-R15).

__device__ unsigned long long g_w1p[80];  // [k*16+p] = (hi=W1[2p+1][k], lo=W1[2p][k])
__device__ int g_minpop;

__global__ void setup_kernel(const float* __restrict__ W1,
                             const float* __restrict__ W2)
{
    int t = threadIdx.x;
    if (t < 80) {
        int k = t >> 4, p = t & 15;
        unsigned lo = __float_as_uint(W1[(2 * p) * 5 + k]);
        unsigned hi = __float_as_uint(W1[(2 * p + 1) * 5 + k]);
        g_w1p[t] = ((unsigned long long)hi << 32) | (unsigned long long)lo;
    }
    if (t >= 96 && t < 128) {   // exactly one full warp
        int i = t - 96;
        float mx = W2[i];
        #pragma unroll
        for (int j = 1; j < 32; j++) mx = fmaxf(mx, W2[j * 32 + i]);
        #pragma unroll
        for (int s = 16; s > 0; s >>= 1)
            mx = fmaxf(mx, __shfl_xor_sync(0xffffffffu, mx, s));
        if (i == 0) {
            int mp = 1;  // smallest popc whose bound popc*cmax could round to >= 2
            while (mp < 33 && (float)mp * mx < 1.99f) mp++;
            g_minpop = mp;
        }
    }
}

__device__ __forceinline__ unsigned long long mul2(unsigned long long a,
                                                   unsigned long long b) {
    unsigned long long d;
    asm("mul.rn.f32x2 %0, %1, %2;" : "=l"(d) : "l"(a), "l"(b));
    return d;
}
__device__ __forceinline__ unsigned long long fma2(unsigned long long a,
                                                   unsigned long long b,
                                                   unsigned long long c) {
    unsigned long long d;
    asm("fma.rn.f32x2 %0, %1, %2, %3;" : "=l"(d) : "l"(a), "l"(b), "l"(c));
    return d;
}
__device__ __forceinline__ unsigned long long add2(unsigned long long a,
                                                   unsigned long long b) {
    unsigned long long d;
    asm("add.rn.f32x2 %0, %1, %2;" : "=l"(d) : "l"(a), "l"(b));
    return d;
}

// exact layers 2-4 (rare, ~1e-4 of rows); identical to R1-R15 validated code.
__device__ __noinline__ unsigned rare_path(unsigned mask1,
                                           const float* __restrict__ W2,
                                           const float* __restrict__ W3,
                                           const float* __restrict__ W4)
{
    unsigned mask2 = 0;
    #pragma unroll
    for (int jc = 0; jc < 32; jc += 8) {
        float acc[8] = {0, 0, 0, 0, 0, 0, 0, 0};
        unsigned mm = mask1;
        while (mm) {
            int i = __ffs(mm) - 1; mm &= mm - 1;
            #pragma unroll
            for (int j = 0; j < 8; j++) acc[j] += W2[(jc + j) * 32 + i];
        }
        #pragma unroll
        for (int j = 0; j < 8; j++)
            if (acc[j] >= 2.0f) mask2 |= 1u << (jc + j);
    }
    if (!mask2) return 0;

    unsigned mask3 = 0;
    #pragma unroll
    for (int jc = 0; jc < 16; jc += 8) {
        float acc[8] = {0, 0, 0, 0, 0, 0, 0, 0};
        unsigned mm = mask2;
        while (mm) {
            int i = __ffs(mm) - 1; mm &= mm - 1;
            #pragma unroll
            for (int j = 0; j < 8; j++) acc[j] += W3[(jc + j) * 32 + i];
        }
        #pragma unroll
        for (int j = 0; j < 8; j++)
            if (acc[j] >= 2.0f) mask3 |= 1u << (jc + j);
    }
    if (!mask3) return 0;

    float acc4[10];
    #pragma unroll
    for (int j = 0; j < 10; j++) acc4[j] = 0.0f;
    unsigned mm = mask3;
    while (mm) {
        int i = __ffs(mm) - 1; mm &= mm - 1;
        #pragma unroll
        for (int j = 0; j < 10; j++) acc4[j] += W4[j * 16 + i];
    }
    unsigned om = 0;
    #pragma unroll
    for (int j = 0; j < 10; j++)
        if (acc4[j] >= 2.0f) om |= 1u << j;
    return om;
}

#define BT 256

__global__ __launch_bounds__(BT)
void snn_kernel(const float* __restrict__ x,
                const float* __restrict__ W2,
                const float* __restrict__ W3,
                const float* __restrict__ W4,
                float* __restrict__ out)
{
    __shared__ unsigned long long sW[80];   // paired W1, 640B

    const int tid = threadIdx.x;
    const size_t row = (size_t)blockIdx.x * BT + tid;
    const int mp = g_minpop;

    if (tid < 40)
        reinterpret_cast<float4*>(sW)[tid] =
            reinterpret_cast<const float4*>(g_w1p)[tid];

    // zero-fill this block's output tile: 640 coalesced STG.128 (R8 pattern)
    {
        float4* ov = reinterpret_cast<float4*>(out + (size_t)blockIdx.x * (BT * 10));
        const float4 z = make_float4(0.f, 0.f, 0.f, 0.f);
        ov[tid] = z;
        ov[tid + 256] = z;
        if (tid < 128) ov[tid + 512] = z;
    }

    // direct x reads (R8-validated path), packed once into f32x2 duplicates
    const float* xr = x + row * 5;
    unsigned long long xp[5];
    #pragma unroll
    for (int k = 0; k < 5; k++) {
        float v = __ldg(xr + k);
        asm("mov.b64 %0, {%1,%1};" : "=l"(xp[k]) : "f"(v));
    }

    __syncthreads();   // sW ready; zero-fill STGs ordered before rare scatter

    uint32_t swa;
    asm("{ .reg .u64 t; cvta.to.shared.u64 t, %1; cvt.u32.u64 %0, t; }"
        : "=r"(swa) : "l"(sW));

    const unsigned long long M2 = 0xC0000000C0000000ULL;   // (-2.0f, -2.0f)
    unsigned nm = 0;   // nonspike mask

    #pragma unroll
    for (int pp = 0; pp < 8; pp++) {      // 2 pairs = 4 outputs per iter
        unsigned long long accA, accB;
        #pragma unroll
        for (int k = 0; k < 5; k++) {
            unsigned long long wA, wB;    // pairs (2pp) and (2pp+1) for this k
            asm("ld.shared.v2.u64 {%0,%1}, [%2];"
                : "=l"(wA), "=l"(wB)
                : "r"(swa + (unsigned)((k * 16 + 2 * pp) * 8)));
            if (k == 0) { accA = mul2(wA, xp[0]); accB = mul2(wB, xp[0]); }
            else        { accA = fma2(wA, xp[k], accA); accB = fma2(wB, xp[k], accB); }
        }
        // d = a - 2 (exact sign); nonspike <=> sign bit set
        unsigned long long dA = add2(accA, M2);
        unsigned long long dB = add2(accB, M2);
        const unsigned aLo = (unsigned)dA, aHi = (unsigned)(dA >> 32);
        const unsigned bLo = (unsigned)dB, bHi = (unsigned)(dB >> 32);
        const int o = 4 * pp;
        nm |= (aLo >> (31 - o)) & (1u << o);
        nm |= (aHi >> (30 - o)) & (2u << o);
        nm |= (bLo >> (29 - o)) & (4u << o);
        nm |= (bHi >> (28 - o)) & (8u << o);
    }

    const unsigned mask1 = ~nm;
    // gate (~1e-4 taken); rare path exact
    if (32 - __popc(nm) >= mp) {
        unsigned om = rare_path(mask1, W2, W3, W4);
        if (om) {
            float* o = out + row * 10;
            #pragma unroll
            for (int j = 0; j < 10; j++)
                o[j] = ((om >> j) & 1u) ? 1.0f : 0.0f;
        }
    }
}

extern "C" void kernel_launch(void* const* d_in, const int* in_sizes, int n_in,
                              void* d_out, int out_size)
{
    const float* x  = (const float*)d_in[0];
    const float* W1 = (const float*)d_in[1];
    const float* W2 = (const float*)d_in[2];
    const float* W3 = (const float*)d_in[3];
    const float* W4 = (const float*)d_in[4];
    float* out = (float*)d_out;

    const int B = in_sizes[0] / 5;        // 2097152
    const int grid = B / BT;              // 8192

    setup_kernel<<<1, 128>>>(W1, W2);
    snn_kernel<<<grid, BT>>>(x, W2, W3, W4, out);
}